// round 9
// baseline (speedup 1.0000x reference)
#include <cuda_runtime.h>
#include <math.h>
#include <stdint.h>

#define NP 5
#define NH 64

typedef unsigned long long u64;

__device__ __forceinline__ u64 pk2(float lo, float hi) {
    u64 r; asm("mov.b64 %0,{%1,%2};" : "=l"(r) : "f"(lo), "f"(hi)); return r;
}
__device__ __forceinline__ void upk2(float& lo, float& hi, u64 v) {
    asm("mov.b64 {%0,%1},%2;" : "=f"(lo), "=f"(hi) : "l"(v));
}
__device__ __forceinline__ u64 f2fma(u64 a, u64 b, u64 c) {
    u64 r; asm("fma.rn.f32x2 %0,%1,%2,%3;" : "=l"(r) : "l"(a), "l"(b), "l"(c)); return r;
}
__device__ __forceinline__ u64 f2mul(u64 a, u64 b) {
    u64 r; asm("mul.rn.f32x2 %0,%1,%2;" : "=l"(r) : "l"(a), "l"(b)); return r;
}
__device__ __forceinline__ float ex2f(float x) {
    float r; asm("ex2.approx.ftz.f32 %0,%1;" : "=f"(r) : "f"(x)); return r;
}
__device__ __forceinline__ float tanhf_a(float x) {
    float r; asm("tanh.approx.f32 %0,%1;" : "=f"(r) : "f"(x)); return r;
}
__device__ __forceinline__ u64 f2ex2(u64 v) {
    float lo, hi; upk2(lo, hi, v); return pk2(ex2f(lo), ex2f(hi));
}
__device__ __forceinline__ u64 f2tanh(u64 v) {
    float lo, hi; upk2(lo, hi, v); return pk2(tanhf_a(lo), tanhf_a(hi));
}

__global__ __launch_bounds__(64, 8)
void topo_kernel(const float* __restrict__ pillars,
                 const float* __restrict__ W1,   // [P][H]
                 const float* __restrict__ b1,
                 const float* __restrict__ W2,
                 const float* __restrict__ b2p,
                 const float* __restrict__ ln_g,
                 const float* __restrict__ ln_b,
                 const float* __restrict__ Wc,
                 const float* __restrict__ bcp,
                 float* __restrict__ out, int n)
{
    // per-h record: {w0,w0}{w1,w1}{w2,w2}{w3,w3}{w4,w4}{bh,bh}{w2h,w2h}{cs,cs} = 64B
    __shared__ __align__(16) float2 sw[NH * 8];
    __shared__ float sg[NP], sbe[NP], sWc[12];
    __shared__ float sb2, sbc;

    const int t = threadIdx.x;
    if (t < NH) {   // blockDim = 64 == NH: exact cover
        float w[NP]; float cn = 0.f;
        #pragma unroll
        for (int j = 0; j < NP; j++) { w[j] = W1[j * NH + t]; cn += w[j] * w[j]; }
        float w2h = W2[t], bh = b1[t];
        float cs = cn * w2h * 0.3989422804f;   // colnorm * W2 * 1/sqrt(2pi)
        float2* d = &sw[t * 8];
        #pragma unroll
        for (int j = 0; j < NP; j++) d[j] = make_float2(w[j], w[j]);
        d[5] = make_float2(bh, bh);
        d[6] = make_float2(w2h, w2h);
        d[7] = make_float2(cs, cs);
    }
    if (t < NP)  { sg[t] = ln_g[t]; sbe[t] = ln_b[t]; }
    if (t < 12)  sWc[t] = Wc[t];
    if (t == 0)  { sb2 = b2p[0]; sbc = bcp[0]; }
    __syncthreads();

    const int base = (blockIdx.x * 64 + t) * 4;   // 4 samples per thread
    if (base >= n) return;
    const bool full = (base + 3 < n);

    // --- load 4 samples (20 floats, 16B-aligned) + sanitize + layernorm ---
    float raw[20];
    if (full) {
        const float4* pp = reinterpret_cast<const float4*>(pillars + base * NP);
        #pragma unroll
        for (int q = 0; q < 5; q++) {
            float4 v = pp[q];
            raw[q * 4 + 0] = v.x; raw[q * 4 + 1] = v.y;
            raw[q * 4 + 2] = v.z; raw[q * 4 + 3] = v.w;
        }
    } else {
        #pragma unroll
        for (int s = 0; s < 4; s++) {
            int i = min(base + s, n - 1);
            #pragma unroll
            for (int j = 0; j < NP; j++) raw[s * 5 + j] = pillars[i * NP + j];
        }
    }

    float ps[4][NP], xs[4][NP];
    #pragma unroll
    for (int s = 0; s < 4; s++) {
        #pragma unroll
        for (int j = 0; j < NP; j++) {
            float v = raw[s * 5 + j];
            float c = isnan(v) ? 0.5f : v;
            ps[s][j] = fminf(fmaxf(c, 0.f), 1.f);
        }
        float mu = 0.f;
        #pragma unroll
        for (int j = 0; j < NP; j++) mu += ps[s][j];
        mu *= 0.2f;
        float var = 0.f;
        #pragma unroll
        for (int j = 0; j < NP; j++) { float d = ps[s][j] - mu; var += d * d; }
        var *= 0.2f;
        float is = rsqrtf(var + 1e-5f);
        #pragma unroll
        for (int j = 0; j < NP; j++) xs[s][j] = (ps[s][j] - mu) * is * sg[j] + sbe[j];
    }

    u64 p2a[NP], x2a[NP], p2b[NP], x2b[NP];
    #pragma unroll
    for (int j = 0; j < NP; j++) {
        p2a[j] = pk2(ps[0][j], ps[1][j]); x2a[j] = pk2(xs[0][j], xs[1][j]);
        p2b[j] = pk2(ps[2][j], ps[3][j]); x2b[j] = pk2(xs[2][j], xs[3][j]);
    }

    // packed constants
    const u64 C_NHL2E = pk2(-0.72134752044f, -0.72134752044f); // -log2(e)/2
    const u64 C_IS2PI = pk2(0.3989422804f, 0.3989422804f);     // 1/sqrt(2pi)
    const u64 C_HALF  = pk2(0.5f, 0.5f);
    const u64 C_TWO   = pk2(2.0f, 2.0f);
    const u64 C_NEG1  = pk2(-1.0f, -1.0f);
    const u64 C_PA    = pk2(0.7988f, 0.7988f);
    const u64 C_PB    = pk2(0.035282996f, 0.035282996f);

    u64 Z = pk2(0.f, 0.f);
    u64 V2a = Z, tr2a = Z, V2b = Z, tr2b = Z;
    u64 g2a[NP] = {Z, Z, Z, Z, Z};
    u64 g2b[NP] = {Z, Z, Z, Z, Z};

    const ulonglong2* sp = reinterpret_cast<const ulonglong2*>(sw);

    #pragma unroll 4
    for (int h = 0; h < NH; h++) {
        ulonglong2 q01 = sp[h * 4 + 0];
        ulonglong2 q23 = sp[h * 4 + 1];
        ulonglong2 q45 = sp[h * 4 + 2];
        ulonglong2 q67 = sp[h * 4 + 3];

        // chain A
        u64 z1a = f2fma(p2a[0], q01.x, q45.y);
        u64 z1b = f2fma(p2b[0], q01.x, q45.y);
        z1a = f2fma(p2a[1], q01.y, z1a);  z1b = f2fma(p2b[1], q01.y, z1b);
        z1a = f2fma(p2a[2], q23.x, z1a);  z1b = f2fma(p2b[2], q23.x, z1b);
        z1a = f2fma(p2a[3], q23.y, z1a);  z1b = f2fma(p2b[3], q23.y, z1b);
        z1a = f2fma(p2a[4], q45.x, z1a);  z1b = f2fma(p2b[4], q45.x, z1b);

        u64 z2a = f2fma(x2a[0], q01.x, q45.y);
        u64 z2b = f2fma(x2b[0], q01.x, q45.y);
        z2a = f2fma(x2a[1], q01.y, z2a);  z2b = f2fma(x2b[1], q01.y, z2b);
        z2a = f2fma(x2a[2], q23.x, z2a);  z2b = f2fma(x2b[2], q23.x, z2b);
        z2a = f2fma(x2a[3], q23.y, z2a);  z2b = f2fma(x2b[3], q23.y, z2b);
        z2a = f2fma(x2a[4], q45.x, z2a);  z2b = f2fma(x2b[4], q45.x, z2b);

        u64 sq1a = f2mul(z1a, z1a);       u64 sq1b = f2mul(z1b, z1b);
        u64 e1a  = f2ex2(f2mul(sq1a, C_NHL2E));
        u64 e1b  = f2ex2(f2mul(sq1b, C_NHL2E));
        u64 ph1a = f2mul(e1a, C_IS2PI);   u64 ph1b = f2mul(e1b, C_IS2PI);

        u64 sq2a = f2mul(z2a, z2a);       u64 sq2b = f2mul(z2b, z2b);
        u64 e2a  = f2ex2(f2mul(sq2a, C_NHL2E));
        u64 e2b  = f2ex2(f2mul(sq2b, C_NHL2E));

        u64 ina = f2fma(sq1a, C_PB, C_PA);
        u64 inb = f2fma(sq1b, C_PB, C_PA);
        u64 tha = f2tanh(f2mul(z1a, ina));
        u64 thb = f2tanh(f2mul(z1b, inb));
        u64 Pha = f2fma(C_HALF, tha, C_HALF);
        u64 Phb = f2fma(C_HALF, thb, C_HALF);

        V2a = f2fma(f2mul(z1a, Pha), q67.x, V2a);
        V2b = f2fma(f2mul(z1b, Phb), q67.x, V2b);

        u64 sa = f2mul(f2fma(z1a, ph1a, Pha), q67.x);
        u64 sb = f2mul(f2fma(z1b, ph1b, Phb), q67.x);
        g2a[0] = f2fma(q01.x, sa, g2a[0]);  g2b[0] = f2fma(q01.x, sb, g2b[0]);
        g2a[1] = f2fma(q01.y, sa, g2a[1]);  g2b[1] = f2fma(q01.y, sb, g2b[1]);
        g2a[2] = f2fma(q23.x, sa, g2a[2]);  g2b[2] = f2fma(q23.x, sb, g2b[2]);
        g2a[3] = f2fma(q23.y, sa, g2a[3]);  g2b[3] = f2fma(q23.y, sb, g2b[3]);
        g2a[4] = f2fma(q45.x, sa, g2a[4]);  g2b[4] = f2fma(q45.x, sb, g2b[4]);

        u64 tma = f2mul(e2a, f2fma(sq2a, C_NEG1, C_TWO));
        u64 tmb = f2mul(e2b, f2fma(sq2b, C_NEG1, C_TWO));
        tr2a = f2fma(q67.y, tma, tr2a);
        tr2b = f2fma(q67.y, tmb, tr2b);
    }

    // --- epilogue: reload raw (L2-hot), finish 4 samples ---
    if (full) {
        const float4* pp = reinterpret_cast<const float4*>(pillars + base * NP);
        #pragma unroll
        for (int q = 0; q < 5; q++) {
            float4 v = pp[q];
            raw[q * 4 + 0] = v.x; raw[q * 4 + 1] = v.y;
            raw[q * 4 + 2] = v.z; raw[q * 4 + 3] = v.w;
        }
    } else {
        #pragma unroll
        for (int s = 0; s < 4; s++) {
            int i = min(base + s, n - 1);
            #pragma unroll
            for (int j = 0; j < NP; j++) raw[s * 5 + j] = pillars[i * NP + j];
        }
    }

    float Vv[4], em[4], gg[4][NP];
    {
        float lo, hi;
        upk2(lo, hi, V2a);  Vv[0] = lo + sb2; Vv[1] = hi + sb2;
        upk2(lo, hi, V2b);  Vv[2] = lo + sb2; Vv[3] = hi + sb2;
        upk2(lo, hi, tr2a); em[0] = lo * 0.2f; em[1] = hi * 0.2f;
        upk2(lo, hi, tr2b); em[2] = lo * 0.2f; em[3] = hi * 0.2f;
        #pragma unroll
        for (int j = 0; j < NP; j++) {
            upk2(lo, hi, g2a[j]); gg[0][j] = lo; gg[1][j] = hi;
            upk2(lo, hi, g2b[j]); gg[2][j] = lo; gg[3][j] = hi;
        }
    }

    #pragma unroll
    for (int s = 0; s < 4; s++) {
        if (base + s >= n) break;
        const float* rw = &raw[s * 5];
        float ss = Vv[s] * Vv[s] + em[s] * em[s];
        #pragma unroll
        for (int j = 0; j < NP; j++) ss += rw[j] * rw[j] + gg[s][j] * gg[s][j];
        float invn = 1.0f / fmaxf(sqrtf(ss), 1e-12f);
        float dot = 0.f;
        #pragma unroll
        for (int j = 0; j < NP; j++) dot += rw[j] * sWc[j];
        #pragma unroll
        for (int j = 0; j < NP; j++) dot += gg[s][j] * sWc[NP + j];
        dot += Vv[s] * sWc[10] + em[s] * sWc[11];
        float logit = sbc + dot * invn;
        float prob = 1.0f / (1.0f + __expf(-logit));
        out[base + s] = fminf(fmaxf(prob, 0.f), 1.f);
    }
}

extern "C" void kernel_launch(void* const* d_in, const int* in_sizes, int n_in,
                              void* d_out, int out_size) {
    const float* pillars = (const float*)d_in[0];
    const float* W1      = (const float*)d_in[1];
    const float* b1      = (const float*)d_in[2];
    const float* W2      = (const float*)d_in[3];
    const float* b2      = (const float*)d_in[4];
    const float* ln_g    = (const float*)d_in[5];
    const float* ln_b    = (const float*)d_in[6];
    const float* Wc      = (const float*)d_in[7];
    const float* bc      = (const float*)d_in[8];
    float* out = (float*)d_out;
    int n = out_size;
    int quads = (n + 3) / 4;
    int threads = 64;
    int blocks = (quads + threads - 1) / threads;
    topo_kernel<<<blocks, threads>>>(pillars, W1, b1, W2, b2, ln_g, ln_b, Wc, bc, out, n);
}

// round 10
// speedup vs baseline: 1.0968x; 1.0968x over previous
#include <cuda_runtime.h>
#include <math.h>
#include <stdint.h>

#define NP 5
#define NH 64

typedef unsigned long long u64;

__device__ __forceinline__ u64 pk2(float lo, float hi) {
    u64 r; asm("mov.b64 %0,{%1,%2};" : "=l"(r) : "f"(lo), "f"(hi)); return r;
}
__device__ __forceinline__ void upk2(float& lo, float& hi, u64 v) {
    asm("mov.b64 {%0,%1},%2;" : "=f"(lo), "=f"(hi) : "l"(v));
}
__device__ __forceinline__ u64 f2fma(u64 a, u64 b, u64 c) {
    u64 r; asm("fma.rn.f32x2 %0,%1,%2,%3;" : "=l"(r) : "l"(a), "l"(b), "l"(c)); return r;
}
__device__ __forceinline__ u64 f2mul(u64 a, u64 b) {
    u64 r; asm("mul.rn.f32x2 %0,%1,%2;" : "=l"(r) : "l"(a), "l"(b)); return r;
}
__device__ __forceinline__ float ex2f(float x) {
    float r; asm("ex2.approx.ftz.f32 %0,%1;" : "=f"(r) : "f"(x)); return r;
}
__device__ __forceinline__ float tanhf_a(float x) {
    float r; asm("tanh.approx.f32 %0,%1;" : "=f"(r) : "f"(x)); return r;
}
__device__ __forceinline__ u64 f2ex2(u64 v) {
    float lo, hi; upk2(lo, hi, v); return pk2(ex2f(lo), ex2f(hi));
}
__device__ __forceinline__ u64 f2tanh(u64 v) {
    float lo, hi; upk2(lo, hi, v); return pk2(tanhf_a(lo), tanhf_a(hi));
}

__global__ __launch_bounds__(64, 14)
void topo_kernel(const float* __restrict__ pillars,
                 const float* __restrict__ W1,   // [P][H]
                 const float* __restrict__ b1,
                 const float* __restrict__ W2,
                 const float* __restrict__ b2p,
                 const float* __restrict__ ln_g,
                 const float* __restrict__ ln_b,
                 const float* __restrict__ Wc,
                 const float* __restrict__ bcp,
                 float* __restrict__ out, int n)
{
    // per-h record: {w0,w0}{w1,w1}{w2,w2}{w3,w3}{w4,w4}{bh,bh}{w2h,w2h}{cs,cs} = 64B
    __shared__ __align__(16) float2 sw[NH * 8];
    __shared__ float sg[NP], sbe[NP], sWc[12];
    __shared__ float sb2, sbc;

    const int t = threadIdx.x;
    if (t < NH) {   // blockDim = 64 == NH: exact cover
        float w[NP]; float cn = 0.f;
        #pragma unroll
        for (int j = 0; j < NP; j++) { w[j] = W1[j * NH + t]; cn += w[j] * w[j]; }
        float w2h = W2[t], bh = b1[t];
        float cs = cn * w2h * 0.3989422804f;   // colnorm * W2 * 1/sqrt(2pi)
        float2* d = &sw[t * 8];
        #pragma unroll
        for (int j = 0; j < NP; j++) d[j] = make_float2(w[j], w[j]);
        d[5] = make_float2(bh, bh);
        d[6] = make_float2(w2h, w2h);
        d[7] = make_float2(cs, cs);
    }
    if (t < NP)  { sg[t] = ln_g[t]; sbe[t] = ln_b[t]; }
    if (t < 12)  sWc[t] = Wc[t];
    if (t == 0)  { sb2 = b2p[0]; sbc = bcp[0]; }
    __syncthreads();

    const int pairIdx = blockIdx.x * 64 + t;
    const int i0 = 2 * pairIdx;
    if (i0 >= n) return;
    const int i1 = (i0 + 1 < n) ? (i0 + 1) : i0;   // tail: duplicate

    // --- load + sanitize (raw NOT kept live across the loop) ---
    float pA[NP], pB[NP];
    #pragma unroll
    for (int j = 0; j < NP; j++) {
        float va = pillars[i0 * NP + j];
        float vb = pillars[i1 * NP + j];
        float ca = isnan(va) ? 0.5f : va;
        float cb = isnan(vb) ? 0.5f : vb;
        pA[j] = fminf(fmaxf(ca, 0.f), 1.f);
        pB[j] = fminf(fmaxf(cb, 0.f), 1.f);
    }

    // --- layernorm ---
    float xA[NP], xB[NP];
    {
        float mu = 0.f; for (int j = 0; j < NP; j++) mu += pA[j]; mu *= 0.2f;
        float var = 0.f; for (int j = 0; j < NP; j++) { float d = pA[j] - mu; var += d * d; } var *= 0.2f;
        float is = rsqrtf(var + 1e-5f);
        #pragma unroll
        for (int j = 0; j < NP; j++) xA[j] = (pA[j] - mu) * is * sg[j] + sbe[j];
    }
    {
        float mu = 0.f; for (int j = 0; j < NP; j++) mu += pB[j]; mu *= 0.2f;
        float var = 0.f; for (int j = 0; j < NP; j++) { float d = pB[j] - mu; var += d * d; } var *= 0.2f;
        float is = rsqrtf(var + 1e-5f);
        #pragma unroll
        for (int j = 0; j < NP; j++) xB[j] = (pB[j] - mu) * is * sg[j] + sbe[j];
    }

    u64 p2[NP], x2[NP];
    #pragma unroll
    for (int j = 0; j < NP; j++) { p2[j] = pk2(pA[j], pB[j]); x2[j] = pk2(xA[j], xB[j]); }

    // packed constants
    const u64 C_NHL2E = pk2(-0.72134752044f, -0.72134752044f); // -log2(e)/2
    const u64 C_IS2PI = pk2(0.3989422804f, 0.3989422804f);     // 1/sqrt(2pi)
    const u64 C_HALF  = pk2(0.5f, 0.5f);
    const u64 C_TWO   = pk2(2.0f, 2.0f);
    const u64 C_NEG1  = pk2(-1.0f, -1.0f);
    const u64 C_PA    = pk2(0.7988f, 0.7988f);
    const u64 C_PB    = pk2(0.035282996f, 0.035282996f);

    u64 V2 = pk2(0.f, 0.f), tr2 = V2;
    u64 g2[NP] = {V2, V2, V2, V2, V2};

    const ulonglong2* sp = reinterpret_cast<const ulonglong2*>(sw);

    #pragma unroll 8
    for (int h = 0; h < NH; h++) {
        ulonglong2 q01 = sp[h * 4 + 0];   // {w0,w0},{w1,w1}
        ulonglong2 q23 = sp[h * 4 + 1];   // {w2,w2},{w3,w3}
        ulonglong2 q45 = sp[h * 4 + 2];   // {w4,w4},{bh,bh}
        ulonglong2 q67 = sp[h * 4 + 3];   // {w2h,w2h},{cs,cs}

        u64 z1 = f2fma(p2[0], q01.x, q45.y);
        z1 = f2fma(p2[1], q01.y, z1);
        z1 = f2fma(p2[2], q23.x, z1);
        z1 = f2fma(p2[3], q23.y, z1);
        z1 = f2fma(p2[4], q45.x, z1);

        u64 z2 = f2fma(x2[0], q01.x, q45.y);
        z2 = f2fma(x2[1], q01.y, z2);
        z2 = f2fma(x2[2], q23.x, z2);
        z2 = f2fma(x2[3], q23.y, z2);
        z2 = f2fma(x2[4], q45.x, z2);

        u64 sq1  = f2mul(z1, z1);
        u64 e1   = f2ex2(f2mul(sq1, C_NHL2E));    // exp(-z1^2/2)
        u64 phi1 = f2mul(e1, C_IS2PI);            // N(0,1) pdf at z1

        u64 sq2  = f2mul(z2, z2);
        u64 e2   = f2ex2(f2mul(sq2, C_NHL2E));    // exp(-z2^2/2)

        // Phi(z1) via tanh-cubic
        u64 inner = f2fma(sq1, C_PB, C_PA);
        u64 arg   = f2mul(z1, inner);
        u64 th    = f2tanh(arg);
        u64 Phi   = f2fma(C_HALF, th, C_HALF);

        // V += gelu(z1)*w2h
        u64 zPhi = f2mul(z1, Phi);
        V2 = f2fma(zPhi, q67.x, V2);

        // s = gelu'(z1)*w2h = (Phi + z1*phi1)*w2h
        u64 s = f2fma(z1, phi1, Phi);
        s = f2mul(s, q67.x);
        g2[0] = f2fma(q01.x, s, g2[0]);
        g2[1] = f2fma(q01.y, s, g2[1]);
        g2[2] = f2fma(q23.x, s, g2[2]);
        g2[3] = f2fma(q23.y, s, g2[3]);
        g2[4] = f2fma(q45.x, s, g2[4]);

        // tr += cs * e2 * (2 - z2^2)
        u64 tm = f2fma(sq2, C_NEG1, C_TWO);
        tm = f2mul(e2, tm);
        tr2 = f2fma(q67.y, tm, tr2);
    }

    // --- epilogue: reload raw pillars (L2-hot) ---
    float rawA[NP], rawB[NP];
    #pragma unroll
    for (int j = 0; j < NP; j++) {
        rawA[j] = pillars[i0 * NP + j];
        rawB[j] = pillars[i1 * NP + j];
    }

    float Va, Vb, tra, trb, ga[NP], gb[NP];
    upk2(Va, Vb, V2); upk2(tra, trb, tr2);
    #pragma unroll
    for (int j = 0; j < NP; j++) upk2(ga[j], gb[j], g2[j]);
    Va += sb2; Vb += sb2;
    float ema = tra * 0.2f, emb = trb * 0.2f;

    {
        float ss = Va * Va + ema * ema;
        #pragma unroll
        for (int j = 0; j < NP; j++) ss += rawA[j] * rawA[j] + ga[j] * ga[j];
        float invn = 1.0f / fmaxf(sqrtf(ss), 1e-12f);
        float dot = 0.f;
        #pragma unroll
        for (int j = 0; j < NP; j++) dot += rawA[j] * sWc[j];
        #pragma unroll
        for (int j = 0; j < NP; j++) dot += ga[j] * sWc[NP + j];
        dot += Va * sWc[10] + ema * sWc[11];
        float logit = sbc + dot * invn;
        float prob = 1.0f / (1.0f + __expf(-logit));
        out[i0] = fminf(fmaxf(prob, 0.f), 1.f);
    }
    if (i0 + 1 < n) {
        float ss = Vb * Vb + emb * emb;
        #pragma unroll
        for (int j = 0; j < NP; j++) ss += rawB[j] * rawB[j] + gb[j] * gb[j];
        float invn = 1.0f / fmaxf(sqrtf(ss), 1e-12f);
        float dot = 0.f;
        #pragma unroll
        for (int j = 0; j < NP; j++) dot += rawB[j] * sWc[j];
        #pragma unroll
        for (int j = 0; j < NP; j++) dot += gb[j] * sWc[NP + j];
        dot += Vb * sWc[10] + emb * sWc[11];
        float logit = sbc + dot * invn;
        float prob = 1.0f / (1.0f + __expf(-logit));
        out[i0 + 1] = fminf(fmaxf(prob, 0.f), 1.f);
    }
}

extern "C" void kernel_launch(void* const* d_in, const int* in_sizes, int n_in,
                              void* d_out, int out_size) {
    const float* pillars = (const float*)d_in[0];
    const float* W1      = (const float*)d_in[1];
    const float* b1      = (const float*)d_in[2];
    const float* W2      = (const float*)d_in[3];
    const float* b2      = (const float*)d_in[4];
    const float* ln_g    = (const float*)d_in[5];
    const float* ln_b    = (const float*)d_in[6];
    const float* Wc      = (const float*)d_in[7];
    const float* bc      = (const float*)d_in[8];
    float* out = (float*)d_out;
    int n = out_size;
    int pairs = (n + 1) / 2;
    int threads = 64;
    int blocks = (pairs + threads - 1) / threads;
    topo_kernel<<<blocks, threads>>>(pillars, W1, b1, W2, b2, ln_g, ln_b, Wc, bc, out, n);
}

// round 15
// speedup vs baseline: 1.1274x; 1.0279x over previous
#include <cuda_runtime.h>
#include <math.h>
#include <stdint.h>

#define NP 5
#define NH 64

typedef unsigned long long u64;

__device__ __forceinline__ u64 pk2(float lo, float hi) {
    u64 r; asm("mov.b64 %0,{%1,%2};" : "=l"(r) : "f"(lo), "f"(hi)); return r;
}
__device__ __forceinline__ void upk2(float& lo, float& hi, u64 v) {
    asm("mov.b64 {%0,%1},%2;" : "=f"(lo), "=f"(hi) : "l"(v));
}
__device__ __forceinline__ u64 f2fma(u64 a, u64 b, u64 c) {
    u64 r; asm("fma.rn.f32x2 %0,%1,%2,%3;" : "=l"(r) : "l"(a), "l"(b), "l"(c)); return r;
}
__device__ __forceinline__ u64 f2mul(u64 a, u64 b) {
    u64 r; asm("mul.rn.f32x2 %0,%1,%2;" : "=l"(r) : "l"(a), "l"(b)); return r;
}
__device__ __forceinline__ float ex2f(float x) {
    float r; asm("ex2.approx.ftz.f32 %0,%1;" : "=f"(r) : "f"(x)); return r;
}
__device__ __forceinline__ float tanhf_a(float x) {
    float r; asm("tanh.approx.f32 %0,%1;" : "=f"(r) : "f"(x)); return r;
}
__device__ __forceinline__ u64 f2ex2(u64 v) {
    float lo, hi; upk2(lo, hi, v); return pk2(ex2f(lo), ex2f(hi));
}
__device__ __forceinline__ u64 f2tanh(u64 v) {
    float lo, hi; upk2(lo, hi, v); return pk2(tanhf_a(lo), tanhf_a(hi));
}

__global__ __launch_bounds__(64)
void topo_kernel(const float* __restrict__ pillars,
                 const float* __restrict__ W1,   // [P][H]
                 const float* __restrict__ b1,
                 const float* __restrict__ W2,
                 const float* __restrict__ b2p,
                 const float* __restrict__ ln_g,
                 const float* __restrict__ ln_b,
                 const float* __restrict__ Wc,
                 const float* __restrict__ bcp,
                 float* __restrict__ out, int n)
{
    // per-h record (12 float2 slots = 96B):
    // 0..4: {wj,wj}  5:{bh,bh}  6:{w2h,w2h}  7:{cs2,cs2}  8:{csn,csn}
    // 9:{Sh,Sh}  10:{Behbh,Behbh}  11: pad
    __shared__ __align__(16) float2 sw[NH * 12];
    __shared__ float sg[NP], sbe[NP], sWc[12];
    __shared__ float sb2, sbc, sg0;
    __shared__ int sflag;

    const int t = threadIdx.x;
    if (t < NP)  { sg[t] = ln_g[t]; sbe[t] = ln_b[t]; }
    if (t < 12)  sWc[t] = Wc[t];
    if (t == 0)  {
        sb2 = b2p[0]; sbc = bcp[0];
        float g0 = ln_g[0];
        sg0 = g0;
        sflag = (ln_g[1] == g0 && ln_g[2] == g0 && ln_g[3] == g0 && ln_g[4] == g0) ? 1 : 0;
    }
    if (t < NH) {   // blockDim = 64 == NH: exact cover
        float w[NP]; float cn = 0.f, Sh = 0.f, Beh = 0.f;
        #pragma unroll
        for (int j = 0; j < NP; j++) {
            w[j] = W1[j * NH + t];
            cn += w[j] * w[j];
            Sh += w[j];
            Beh += ln_b[j] * w[j];
        }
        float w2h = W2[t], bh = b1[t];
        float cs = cn * w2h * 0.3989422804f;   // colnorm * W2 * 1/sqrt(2pi)
        float2* d = &sw[t * 12];
        #pragma unroll
        for (int j = 0; j < NP; j++) d[j] = make_float2(w[j], w[j]);
        d[5]  = make_float2(bh, bh);
        d[6]  = make_float2(w2h, w2h);
        d[7]  = make_float2(2.0f * cs, 2.0f * cs);
        d[8]  = make_float2(-cs, -cs);
        d[9]  = make_float2(Sh, Sh);
        d[10] = make_float2(Beh + bh, Beh + bh);
        d[11] = make_float2(0.f, 0.f);
    }
    __syncthreads();

    const int pairIdx = blockIdx.x * 64 + t;
    const int i0 = 2 * pairIdx;
    if (i0 >= n) return;
    const int i1 = (i0 + 1 < n) ? (i0 + 1) : i0;   // tail: duplicate

    // --- load + sanitize (raw kept live; R8-style) ---
    float rawA[NP], rawB[NP], pA[NP], pB[NP];
    #pragma unroll
    for (int j = 0; j < NP; j++) {
        float va = pillars[i0 * NP + j];
        float vb = pillars[i1 * NP + j];
        rawA[j] = va; rawB[j] = vb;
        float ca = isnan(va) ? 0.5f : va;
        float cb = isnan(vb) ? 0.5f : vb;
        pA[j] = fminf(fmaxf(ca, 0.f), 1.f);
        pB[j] = fminf(fmaxf(cb, 0.f), 1.f);
    }

    // --- layernorm stats ---
    float muA = 0.f, muB = 0.f;
    #pragma unroll
    for (int j = 0; j < NP; j++) { muA += pA[j]; muB += pB[j]; }
    muA *= 0.2f; muB *= 0.2f;
    float varA = 0.f, varB = 0.f;
    #pragma unroll
    for (int j = 0; j < NP; j++) {
        float dA = pA[j] - muA; varA += dA * dA;
        float dB = pB[j] - muB; varB += dB * dB;
    }
    float isA = rsqrtf(varA * 0.2f + 1e-5f);
    float isB = rsqrtf(varB * 0.2f + 1e-5f);

    u64 p2[NP];
    #pragma unroll
    for (int j = 0; j < NP; j++) p2[j] = pk2(pA[j], pB[j]);

    // packed constants
    const u64 C_NHL2E = pk2(-0.72134752044f, -0.72134752044f); // -log2(e)/2
    const u64 C_IS2PI = pk2(0.3989422804f, 0.3989422804f);     // 1/sqrt(2pi)
    const u64 C_HALF  = pk2(0.5f, 0.5f);
    const u64 C_PA    = pk2(0.7988f, 0.7988f);
    const u64 C_PB    = pk2(0.035282996f, 0.035282996f);

    u64 V2 = pk2(0.f, 0.f), tr2 = V2;
    u64 g2[NP] = {V2, V2, V2, V2, V2};

    const ulonglong2* sp = reinterpret_cast<const ulonglong2*>(sw);

    if (sflag) {
        // uniform-gamma path: z2 = c*z1 - c*bh - (c*mu)*Sh + (Beh+bh)
        float cA = isA * sg0, cB = isB * sg0;
        const u64 Cc  = pk2(cA, cB);
        const u64 NC  = pk2(-cA, -cB);
        const u64 NCM = pk2(-cA * muA, -cB * muB);

        #pragma unroll 8
        for (int h = 0; h < NH; h++) {
            ulonglong2 L0 = sp[h * 6 + 0];   // w0,w1
            ulonglong2 L1 = sp[h * 6 + 1];   // w2,w3
            ulonglong2 L2 = sp[h * 6 + 2];   // w4,bh
            ulonglong2 L3 = sp[h * 6 + 3];   // w2h,cs2
            ulonglong2 L4 = sp[h * 6 + 4];   // csn,Sh
            ulonglong2 L5 = sp[h * 6 + 5];   // Behbh,pad

            u64 z1 = f2fma(p2[0], L0.x, L2.y);
            z1 = f2fma(p2[1], L0.y, z1);
            z1 = f2fma(p2[2], L1.x, z1);
            z1 = f2fma(p2[3], L1.y, z1);
            z1 = f2fma(p2[4], L2.x, z1);

            u64 k  = f2fma(NCM, L4.y, L5.x);  // -c*mu*Sh + (Beh+bh)
            k      = f2fma(NC, L2.y, k);      // -c*bh + ...
            u64 z2 = f2fma(Cc, z1, k);

            u64 sq1  = f2mul(z1, z1);
            u64 e1   = f2ex2(f2mul(sq1, C_NHL2E));
            u64 phi1 = f2mul(e1, C_IS2PI);

            u64 sq2  = f2mul(z2, z2);
            u64 e2   = f2ex2(f2mul(sq2, C_NHL2E));

            u64 inner = f2fma(sq1, C_PB, C_PA);
            u64 th    = f2tanh(f2mul(z1, inner));
            u64 Phi   = f2fma(C_HALF, th, C_HALF);

            V2 = f2fma(f2mul(z1, Phi), L3.x, V2);

            u64 s = f2mul(f2fma(z1, phi1, Phi), L3.x);
            g2[0] = f2fma(L0.x, s, g2[0]);
            g2[1] = f2fma(L0.y, s, g2[1]);
            g2[2] = f2fma(L1.x, s, g2[2]);
            g2[3] = f2fma(L1.y, s, g2[3]);
            g2[4] = f2fma(L2.x, s, g2[4]);

            u64 tm = f2fma(sq2, L4.x, L3.y);  // csn*sq2 + cs2 = cs*(2 - z2^2)
            tr2 = f2fma(e2, tm, tr2);
        }
    } else {
        // generic path (gamma not uniform): full x matvec
        float xA[NP], xB[NP];
        #pragma unroll
        for (int j = 0; j < NP; j++) {
            xA[j] = (pA[j] - muA) * isA * sg[j] + sbe[j];
            xB[j] = (pB[j] - muB) * isB * sg[j] + sbe[j];
        }
        u64 x2[NP];
        #pragma unroll
        for (int j = 0; j < NP; j++) x2[j] = pk2(xA[j], xB[j]);

        #pragma unroll 8
        for (int h = 0; h < NH; h++) {
            ulonglong2 L0 = sp[h * 6 + 0];
            ulonglong2 L1 = sp[h * 6 + 1];
            ulonglong2 L2 = sp[h * 6 + 2];
            ulonglong2 L3 = sp[h * 6 + 3];
            ulonglong2 L4 = sp[h * 6 + 4];

            u64 z1 = f2fma(p2[0], L0.x, L2.y);
            z1 = f2fma(p2[1], L0.y, z1);
            z1 = f2fma(p2[2], L1.x, z1);
            z1 = f2fma(p2[3], L1.y, z1);
            z1 = f2fma(p2[4], L2.x, z1);

            u64 z2 = f2fma(x2[0], L0.x, L2.y);
            z2 = f2fma(x2[1], L0.y, z2);
            z2 = f2fma(x2[2], L1.x, z2);
            z2 = f2fma(x2[3], L1.y, z2);
            z2 = f2fma(x2[4], L2.x, z2);

            u64 sq1  = f2mul(z1, z1);
            u64 e1   = f2ex2(f2mul(sq1, C_NHL2E));
            u64 phi1 = f2mul(e1, C_IS2PI);

            u64 sq2  = f2mul(z2, z2);
            u64 e2   = f2ex2(f2mul(sq2, C_NHL2E));

            u64 inner = f2fma(sq1, C_PB, C_PA);
            u64 th    = f2tanh(f2mul(z1, inner));
            u64 Phi   = f2fma(C_HALF, th, C_HALF);

            V2 = f2fma(f2mul(z1, Phi), L3.x, V2);

            u64 s = f2mul(f2fma(z1, phi1, Phi), L3.x);
            g2[0] = f2fma(L0.x, s, g2[0]);
            g2[1] = f2fma(L0.y, s, g2[1]);
            g2[2] = f2fma(L1.x, s, g2[2]);
            g2[3] = f2fma(L1.y, s, g2[3]);
            g2[4] = f2fma(L2.x, s, g2[4]);

            u64 tm = f2fma(sq2, L4.x, L3.y);
            tr2 = f2fma(e2, tm, tr2);
        }
    }

    // --- epilogue (scalar per sample) ---
    float Va, Vb, tra, trb, ga[NP], gb[NP];
    upk2(Va, Vb, V2); upk2(tra, trb, tr2);
    #pragma unroll
    for (int j = 0; j < NP; j++) upk2(ga[j], gb[j], g2[j]);
    Va += sb2; Vb += sb2;
    float ema = tra * 0.2f, emb = trb * 0.2f;

    {
        float ss = Va * Va + ema * ema;
        #pragma unroll
        for (int j = 0; j < NP; j++) ss += rawA[j] * rawA[j] + ga[j] * ga[j];
        float invn = 1.0f / fmaxf(sqrtf(ss), 1e-12f);
        float dot = 0.f;
        #pragma unroll
        for (int j = 0; j < NP; j++) dot += rawA[j] * sWc[j];
        #pragma unroll
        for (int j = 0; j < NP; j++) dot += ga[j] * sWc[NP + j];
        dot += Va * sWc[10] + ema * sWc[11];
        float logit = sbc + dot * invn;
        float prob = 1.0f / (1.0f + __expf(-logit));
        out[i0] = fminf(fmaxf(prob, 0.f), 1.f);
    }
    if (i0 + 1 < n) {
        float ss = Vb * Vb + emb * emb;
        #pragma unroll
        for (int j = 0; j < NP; j++) ss += rawB[j] * rawB[j] + gb[j] * gb[j];
        float invn = 1.0f / fmaxf(sqrtf(ss), 1e-12f);
        float dot = 0.f;
        #pragma unroll
        for (int j = 0; j < NP; j++) dot += rawB[j] * sWc[j];
        #pragma unroll
        for (int j = 0; j < NP; j++) dot += gb[j] * sWc[NP + j];
        dot += Vb * sWc[10] + emb * sWc[11];
        float logit = sbc + dot * invn;
        float prob = 1.0f / (1.0f + __expf(-logit));
        out[i0 + 1] = fminf(fmaxf(prob, 0.f), 1.f);
    }
}

extern "C" void kernel_launch(void* const* d_in, const int* in_sizes, int n_in,
                              void* d_out, int out_size) {
    const float* pillars = (const float*)d_in[0];
    const float* W1      = (const float*)d_in[1];
    const float* b1      = (const float*)d_in[2];
    const float* W2      = (const float*)d_in[3];
    const float* b2      = (const float*)d_in[4];
    const float* ln_g    = (const float*)d_in[5];
    const float* ln_b    = (const float*)d_in[6];
    const float* Wc      = (const float*)d_in[7];
    const float* bc      = (const float*)d_in[8];
    float* out = (float*)d_out;
    int n = out_size;
    int pairs = (n + 1) / 2;
    int threads = 64;
    int blocks = (pairs + threads - 1) / threads;
    topo_kernel<<<blocks, threads>>>(pillars, W1, b1, W2, b2, ln_g, ln_b, Wc, bc, out, n);
}